// round 2
// baseline (speedup 1.0000x reference)
#include <cuda_runtime.h>
#include <cstdint>
#include <cstddef>

#define NS 512
#define NB 1024
#define NT 64
#define WARPS_PER_BLOCK 7
#define THREADS_PER_BLOCK (WARPS_PER_BLOCK * 32)

// Per-batch (score - normalizer), reduced by a second kernel.
__device__ float g_partial[NB];

// ---------- packed f32x2 helpers (sm_100+) ----------
__device__ __forceinline__ unsigned long long pack2(float lo, float hi) {
    unsigned long long r;
    asm("mov.b64 %0, {%1, %2};" : "=l"(r) : "f"(lo), "f"(hi));
    return r;
}
__device__ __forceinline__ void unpack2(unsigned long long v, float& lo, float& hi) {
    asm("mov.b64 {%0, %1}, %2;" : "=f"(lo), "=f"(hi) : "l"(v));
}
__device__ __forceinline__ void fma2(unsigned long long& acc,
                                     unsigned long long a, unsigned long long b) {
    asm("fma.rn.f32x2 %0, %1, %2, %0;" : "+l"(acc) : "l"(a), "l"(b));
}
__device__ __forceinline__ unsigned long long add2(unsigned long long a, unsigned long long b) {
    unsigned long long r;
    asm("add.rn.f32x2 %0, %1, %2;" : "=l"(r) : "l"(a), "l"(b));
    return r;
}

__global__ void __launch_bounds__(THREADS_PER_BLOCK, 1)
crf_forward_kernel(const float* __restrict__ em,
                   const float* __restrict__ trans,
                   const float* __restrict__ start_t,
                   const float* __restrict__ end_t,
                   const int* __restrict__ tags,
                   const int* __restrict__ mask) {
    // Double-buffered duplicated-p strips: per warp 2 x 64 x u64 = 1024 B.
    __shared__ __align__(16) unsigned long long pbuf[WARPS_PER_BLOCK][128];

    const int w    = threadIdx.x >> 5;
    const int lane = threadIdx.x & 31;
    const int b    = blockIdx.x * WARPS_PER_BLOCK + w;
    if (b >= NB) return;

    const int c0 = lane * 2;  // this thread's two tag-columns: c0, c0+1

    // ---------------- E = exp(transitions), columns (c0,c0+1) in registers ----------------
    unsigned long long Ecol[NT];
#pragma unroll
    for (int i = 0; i < NT; i++) {
        float2 tr = *reinterpret_cast<const float2*>(trans + i * NT + c0);
        Ecol[i] = pack2(__expf(tr.x), __expf(tr.y));
    }

    // ---------------- numerator: gold-path score (lane-parallel over timesteps) -------------
    float sc = 0.f;
    int msum = 0;
#pragma unroll
    for (int k = 0; k < 16; k++) {
        int s = 1 + lane + (k << 5);
        if (s < NS) {
            int tp = tags[(s - 1) * NB + b];
            int tc = tags[s * NB + b];
            int mv = mask[s * NB + b];
            float term = trans[tp * NT + tc] + em[((size_t)s * NB + b) * NT + tc];
            sc += term * (float)mv;
            msum += mv;
        }
    }
#pragma unroll
    for (int off = 16; off; off >>= 1) {
        sc   += __shfl_xor_sync(0xffffffffu, sc, off);
        msum += __shfl_xor_sync(0xffffffffu, msum, off);
    }
    {   // uniform across lanes after reduction
        int t0 = tags[b];  // tags[0, b]
        sc += start_t[t0] + em[(size_t)b * NT + t0];
        int seq_end = mask[b] + msum - 1;      // sum(mask[:,b]) - 1
        int lt = tags[(size_t)seq_end * NB + b];
        sc += end_t[lt];
    }

    // ---------------- denominator: forward recursion ----------------
    const float* emb = em + (size_t)b * NT + c0;     // em[s,b,c0] at emb + s*NB*NT
    float2 alpha;
    {
        float2 e0 = *reinterpret_cast<const float2*>(emb);
        float2 st = *reinterpret_cast<const float2*>(start_t + c0);
        alpha.x = st.x + e0.x;
        alpha.y = st.y + e0.y;
    }
    float2 em_next = *reinterpret_cast<const float2*>(emb + (size_t)NB * NT);
    unsigned long long* myp = pbuf[w];

    for (int s = 1; s < NS; s++) {
        float2 emc = em_next;
        if (s + 1 < NS)
            em_next = *reinterpret_cast<const float2*>(emb + (size_t)(s + 1) * NB * NT);
        int mk = mask[s * NB + b];

        // warp-wide max of alpha over 64 columns
        float m = fmaxf(alpha.x, alpha.y);
#pragma unroll
        for (int off = 16; off; off >>= 1)
            m = fmaxf(m, __shfl_xor_sync(0xffffffffu, m, off));

        // p = exp(alpha - m), stored lane-duplicated for packed FMA
        float p0 = __expf(alpha.x - m);
        float p1 = __expf(alpha.y - m);
        unsigned long long* buf = myp + ((s & 1) << 6);
        buf[c0]     = pack2(p0, p0);
        buf[c0 + 1] = pack2(p1, p1);
        __syncwarp();

        // matvec: acc(j) = sum_i p[i] * E[i][j], packed over 2 columns
        unsigned long long a0 = 0ull, a1 = 0ull, a2 = 0ull, a3 = 0ull;
#pragma unroll
        for (int i = 0; i < NT; i += 4) {
            ulonglong2 p01 = *reinterpret_cast<const ulonglong2*>(buf + i);
            ulonglong2 p23 = *reinterpret_cast<const ulonglong2*>(buf + i + 2);
            fma2(a0, p01.x, Ecol[i]);
            fma2(a1, p01.y, Ecol[i + 1]);
            fma2(a2, p23.x, Ecol[i + 2]);
            fma2(a3, p23.y, Ecol[i + 3]);
        }
        unsigned long long acc = add2(add2(a0, a1), add2(a2, a3));
        float ax, ay;
        unpack2(acc, ax, ay);

        float nx = m + __logf(ax) + emc.x;
        float ny = m + __logf(ay) + emc.y;
        if (mk) { alpha.x = nx; alpha.y = ny; }
        // no trailing sync needed: double buffer + next iteration's pre-read sync
    }

    // normalizer = logsumexp_j(alpha[j] + end_t[j])
    float2 et = *reinterpret_cast<const float2*>(end_t + c0);
    float vx = alpha.x + et.x, vy = alpha.y + et.y;
    float m2 = fmaxf(vx, vy);
#pragma unroll
    for (int off = 16; off; off >>= 1)
        m2 = fmaxf(m2, __shfl_xor_sync(0xffffffffu, m2, off));
    float se = __expf(vx - m2) + __expf(vy - m2);
#pragma unroll
    for (int off = 16; off; off >>= 1)
        se += __shfl_xor_sync(0xffffffffu, se, off);

    if (lane == 0)
        g_partial[b] = sc - (m2 + __logf(se));
}

__global__ void crf_reduce_kernel(float* __restrict__ out) {
    __shared__ float smem[8];
    int tid = threadIdx.x;
    float s = 0.f;
    for (int i = tid; i < NB; i += 256)
        s += g_partial[i];
#pragma unroll
    for (int off = 16; off; off >>= 1)
        s += __shfl_xor_sync(0xffffffffu, s, off);
    if ((tid & 31) == 0) smem[tid >> 5] = s;
    __syncthreads();
    if (tid < 32) {
        s = (tid < 8) ? smem[tid] : 0.f;
#pragma unroll
        for (int off = 4; off; off >>= 1)
            s += __shfl_xor_sync(0xffffffffu, s, off);
        if (tid == 0) out[0] = s;
    }
}

extern "C" void kernel_launch(void* const* d_in, const int* in_sizes, int n_in,
                              void* d_out, int out_size) {
    const float* em    = (const float*)d_in[0];
    const float* trans = (const float*)d_in[1];
    const float* st    = (const float*)d_in[2];
    const float* et    = (const float*)d_in[3];
    const int*   tags  = (const int*)d_in[4];
    const int*   mask  = (const int*)d_in[5];

    int grid = (NB + WARPS_PER_BLOCK - 1) / WARPS_PER_BLOCK;  // 147
    crf_forward_kernel<<<grid, THREADS_PER_BLOCK>>>(em, trans, st, et, tags, mask);
    crf_reduce_kernel<<<1, 256>>>((float*)d_out);
}

// round 3
// speedup vs baseline: 1.4334x; 1.4334x over previous
#include <cuda_runtime.h>
#include <cstdint>
#include <cstddef>

#define NS 512
#define NB 1024
#define NT 64
#define WARPS_PER_BLOCK 7
#define THREADS_PER_BLOCK (WARPS_PER_BLOCK * 32)

__device__ float g_partial[NB];

typedef unsigned long long u64;

// ---------- packed f32x2 helpers (sm_100+) ----------
__device__ __forceinline__ u64 pack2(float lo, float hi) {
    u64 r; asm("mov.b64 %0, {%1, %2};" : "=l"(r) : "f"(lo), "f"(hi)); return r;
}
__device__ __forceinline__ void unpack2(u64 v, float& lo, float& hi) {
    asm("mov.b64 {%0, %1}, %2;" : "=f"(lo), "=f"(hi) : "l"(v));
}
__device__ __forceinline__ void fma2(u64& acc, u64 a, u64 b) {
    asm("fma.rn.f32x2 %0, %1, %2, %0;" : "+l"(acc) : "l"(a), "l"(b));
}
__device__ __forceinline__ u64 add2(u64 a, u64 b) {
    u64 r; asm("add.rn.f32x2 %0, %1, %2;" : "=l"(r) : "l"(a), "l"(b)); return r;
}
__device__ __forceinline__ u64 mul2(u64 a, u64 b) {
    u64 r; asm("mul.rn.f32x2 %0, %1, %2;" : "=l"(r) : "l"(a), "l"(b)); return r;
}
__device__ __forceinline__ float frcp(float x) {
    float r; asm("rcp.approx.f32 %0, %1;" : "=f"(r) : "f"(x)); return r;
}

__global__ void __launch_bounds__(THREADS_PER_BLOCK, 1)
crf_forward_kernel(const float* __restrict__ em,
                   const float* __restrict__ trans,
                   const float* __restrict__ start_t,
                   const float* __restrict__ end_t,
                   const int* __restrict__ tags,
                   const int* __restrict__ mask) {
    // Double-buffered duplicated-q strips: per warp 2 x 64 x u64 = 1024 B.
    __shared__ __align__(16) u64 pbuf[WARPS_PER_BLOCK][128];

    const int w    = threadIdx.x >> 5;
    const int lane = threadIdx.x & 31;
    const int b    = blockIdx.x * WARPS_PER_BLOCK + w;
    if (b >= NB) return;

    const int c0 = lane * 2;                 // this thread's two tag columns

    // ---------------- numerator: gold-path score (lane-parallel over timesteps) ----------
    float sc = 0.f;
    int msum = 0;
#pragma unroll
    for (int k = 0; k < 16; k++) {
        int s = 1 + lane + (k << 5);
        if (s < NS) {
            int tp = tags[(s - 1) * NB + b];
            int tc = tags[s * NB + b];
            int mv = mask[s * NB + b];
            float term = trans[tp * NT + tc] + em[((size_t)s * NB + b) * NT + tc];
            sc += term * (float)mv;
            msum += mv;
        }
    }
#pragma unroll
    for (int off = 16; off; off >>= 1) {
        sc   += __shfl_xor_sync(0xffffffffu, sc, off);
        msum += __shfl_xor_sync(0xffffffffu, msum, off);
    }
    {
        int t0 = tags[b];
        sc += start_t[t0] + em[(size_t)b * NT + t0];
        int seq_end = mask[b] + msum - 1;
        int lt = tags[(size_t)seq_end * NB + b];
        sc += end_t[lt];
    }

    // ---------------- E = exp(transitions), columns (c0,c0+1) in registers ----------------
    u64 Ecol[NT];
#pragma unroll
    for (int i = 0; i < NT; i++) {
        float2 tr = *reinterpret_cast<const float2*>(trans + i * NT + c0);
        Ecol[i] = pack2(__expf(tr.x), __expf(tr.y));
    }

    // ---------------- denominator: linear-domain forward recursion ----------------
    const float* emb = em + (size_t)b * NT + c0;     // em[s,b,c0] at emb + s*NB*NT
    const size_t SSTR = (size_t)NB * NT;

    float qx, qy;
    {
        float2 e0 = *reinterpret_cast<const float2*>(emb);
        float2 st = *reinterpret_cast<const float2*>(start_t + c0);
        qx = __expf(st.x + e0.x);
        qy = __expf(st.y + e0.y);
    }
    float Mtot = 0.f;
    u64* const myp = pbuf[w];

    // em prefetch ring (4 deep, static via 4x unroll) + exp(em) one step ahead
    float2 pf0 = *reinterpret_cast<const float2*>(emb + 1 * SSTR);
    float2 pf1 = *reinterpret_cast<const float2*>(emb + 2 * SSTR);
    float2 pf2 = *reinterpret_cast<const float2*>(emb + 3 * SSTR);
    float2 pf3 = *reinterpret_cast<const float2*>(emb + 4 * SSTR);
    u64 eemCur = pack2(__expf(pf0.x), __expf(pf0.y));
    int mkA = mask[1 * NB + b];
    int mkB = mask[2 * NB + b];

#define CRF_STEP(S, PAR, PF_USE, PF_WR, MK_SLOT)                                   \
    do {                                                                           \
        if ((S) < NS) {                                                            \
            int mk = MK_SLOT;                                                      \
            u64* buf = myp + ((PAR) << 6);                                         \
            buf[c0]     = pack2(qx, qx);                                           \
            buf[c0 + 1] = pack2(qy, qy);                                           \
            __syncwarp();                                                          \
            u64 A0=0,A1=0,A2=0,A3=0,A4=0,A5=0,A6=0,A7=0;                           \
            _Pragma("unroll")                                                      \
            for (int i = 0; i < NT; i += 8) {                                      \
                ulonglong2 pA = *reinterpret_cast<const ulonglong2*>(buf + i);     \
                ulonglong2 pB = *reinterpret_cast<const ulonglong2*>(buf + i + 2); \
                ulonglong2 pC = *reinterpret_cast<const ulonglong2*>(buf + i + 4); \
                ulonglong2 pD = *reinterpret_cast<const ulonglong2*>(buf + i + 6); \
                fma2(A0, pA.x, Ecol[i]);     fma2(A1, pA.y, Ecol[i + 1]);          \
                fma2(A2, pB.x, Ecol[i + 2]); fma2(A3, pB.y, Ecol[i + 3]);          \
                fma2(A4, pC.x, Ecol[i + 4]); fma2(A5, pC.y, Ecol[i + 5]);          \
                fma2(A6, pD.x, Ecol[i + 6]); fma2(A7, pD.y, Ecol[i + 7]);          \
            }                                                                      \
            u64 acc = add2(add2(add2(A0, A1), add2(A2, A3)),                       \
                           add2(add2(A4, A5), add2(A6, A7)));                      \
            float ax, ay; unpack2(acc, ax, ay);                                    \
            float a0 = __shfl_sync(0xffffffffu, ax, 0);                            \
            float r0 = frcp(a0);                                                   \
            u64 q2 = mul2(mul2(acc, pack2(r0, r0)), eemCur);                       \
            float nqx, nqy; unpack2(q2, nqx, nqy);                                 \
            float lr = __logf(a0);                                                 \
            if (mk) { qx = nqx; qy = nqy; Mtot += lr; }                            \
            eemCur = pack2(__expf(PF_USE.x), __expf(PF_USE.y));                    \
            if ((S) + 4 < NS)                                                      \
                PF_WR = *reinterpret_cast<const float2*>(emb + (size_t)((S) + 4) * SSTR); \
            if ((S) + 2 < NS)                                                      \
                MK_SLOT = mask[((S) + 2) * NB + b];                                \
        }                                                                          \
    } while (0)

    for (int k = 0; k < 128; k++) {
        int sb = 1 + (k << 2);
        CRF_STEP(sb,     1, pf1, pf0, mkA);   // eem next from em[s+1] (slot1), refill slot0 with em[s+4]
        CRF_STEP(sb + 1, 0, pf2, pf1, mkB);
        CRF_STEP(sb + 2, 1, pf3, pf2, mkA);
        CRF_STEP(sb + 3, 0, pf0, pf3, mkB);
    }
#undef CRF_STEP

    // normalizer = Mtot + log( sum_j q_j * exp(end_j) )
    float2 et = *reinterpret_cast<const float2*>(end_t + c0);
    float v = qx * __expf(et.x) + qy * __expf(et.y);
#pragma unroll
    for (int off = 16; off; off >>= 1)
        v += __shfl_xor_sync(0xffffffffu, v, off);

    if (lane == 0)
        g_partial[b] = sc - (Mtot + __logf(v));
}

__global__ void crf_reduce_kernel(float* __restrict__ out) {
    __shared__ float smem[8];
    int tid = threadIdx.x;
    float s = 0.f;
    for (int i = tid; i < NB; i += 256)
        s += g_partial[i];
#pragma unroll
    for (int off = 16; off; off >>= 1)
        s += __shfl_xor_sync(0xffffffffu, s, off);
    if ((tid & 31) == 0) smem[tid >> 5] = s;
    __syncthreads();
    if (tid < 32) {
        s = (tid < 8) ? smem[tid] : 0.f;
#pragma unroll
        for (int off = 4; off; off >>= 1)
            s += __shfl_xor_sync(0xffffffffu, s, off);
        if (tid == 0) out[0] = s;
    }
}

extern "C" void kernel_launch(void* const* d_in, const int* in_sizes, int n_in,
                              void* d_out, int out_size) {
    const float* em    = (const float*)d_in[0];
    const float* trans = (const float*)d_in[1];
    const float* st    = (const float*)d_in[2];
    const float* et    = (const float*)d_in[3];
    const int*   tags  = (const int*)d_in[4];
    const int*   mask  = (const int*)d_in[5];

    int grid = (NB + WARPS_PER_BLOCK - 1) / WARPS_PER_BLOCK;  // 147
    crf_forward_kernel<<<grid, THREADS_PER_BLOCK>>>(em, trans, st, et, tags, mask);
    crf_reduce_kernel<<<1, 256>>>((float*)d_out);
}